// round 2
// baseline (speedup 1.0000x reference)
#include <cuda_runtime.h>
#include <cstdint>

#define NHN 50000
#define NGN 50000
#define NE  1600000
#define NGR 16

// ---------------- scratch (device globals; no allocations) ----------------
__device__ __align__(16) float g_H1[(size_t)NHN * 128];   // x_h@W1aL^T + b1a (pre-activation partial)
__device__ __align__(16) float g_S [(size_t)NGN * 128];   // sum of leaky(z_e) per target node
__device__ __align__(16) float g_T2[(size_t)NGN * 128];   // leaky(node-MLP stage1)
__device__ __align__(16) float g_WtH1[64 * 128];          // W1a[:, :64]^T   -> [k][j]
__device__ __align__(16) float g_WtE [64 * 128];          // W1a[:, 64:]^T   -> [k][j]
__device__ __align__(16) float g_WtN1[256 * 128];         // rows 0:128 = W2a[:, :128]^T ; rows 128:256 = (W2aA@W1b)^T
__device__ __align__(16) float g_WtN2[128 * 128];         // W2b^T
__device__ __align__(16) float g_cvec[128];               // W2aA @ b1b
__device__ __align__(16) float g_UW[NGR * 128];           // u @ W2aU^T
__device__ int g_deg[NGN];
__device__ int g_is64_e;
__device__ int g_is64_b;

// ---------------- dtype detection (int32 vs int64 indices) ----------------
__global__ void k_detect(const void* eidx, const void* batch) {
    if (blockIdx.x == 0 && threadIdx.x == 0) {
        const unsigned* p = (const unsigned*)eidx;
        int is64 = 1;
        for (int i = 0; i < 32; i++) {
            unsigned lo = p[2 * i], hi = p[2 * i + 1];
            if (hi != 0u || lo >= (unsigned)NHN) { is64 = 0; break; }
        }
        g_is64_e = is64;
        const unsigned* q = (const unsigned*)batch;
        int b64 = 1;
        for (int i = 0; i < 32; i++) {
            unsigned lo = q[2 * i], hi = q[2 * i + 1];
            if (hi != 0u || lo >= (unsigned)NGR) { b64 = 0; break; }
        }
        g_is64_b = b64;
    }
}

// ---------------- zero scratch ----------------
__global__ void k_zero() {
    long long n4 = (long long)NGN * 128 / 4;
    long long stride = (long long)gridDim.x * blockDim.x;
    for (long long i = (long long)blockIdx.x * blockDim.x + threadIdx.x; i < n4; i += stride)
        ((float4*)g_S)[i] = make_float4(0.f, 0.f, 0.f, 0.f);
    for (long long i = (long long)blockIdx.x * blockDim.x + threadIdx.x; i < NGN; i += stride)
        g_deg[i] = 0;
}

// ---------------- weight precompute / transposes ----------------
__global__ void k_prep(const float* __restrict__ W1a, const float* __restrict__ W1b,
                       const float* __restrict__ W2a, const float* __restrict__ W2b,
                       const float* __restrict__ b1b, const float* __restrict__ u) {
    int b = blockIdx.x, t = threadIdx.x;
    if (b < 128) {
        // M[j=b][k=t] = sum_p W2a[j,128+p] * W1b[p,k]; stored transposed at g_WtN1[(128+k)*128 + j]
        __shared__ float wrow[128];
        wrow[t] = W2a[b * 320 + 128 + t];
        __syncthreads();
        float s = 0.f;
        for (int p = 0; p < 128; p++) s += wrow[p] * W1b[p * 128 + t];
        g_WtN1[(128 + t) * 128 + b] = s;
        if (t == 0) {
            float c = 0.f;
            for (int p = 0; p < 128; p++) c += wrow[p] * b1b[p];
            g_cvec[b] = c;
        }
    } else if (b == 128) {
        for (int i = t; i < 64 * 128; i += 128) {
            int k = i >> 7, j = i & 127;
            g_WtH1[i] = W1a[j * 128 + k];
            g_WtE[i]  = W1a[j * 128 + 64 + k];
        }
    } else if (b == 129) {
        for (int i = t; i < 128 * 128; i += 128) {
            int k = i >> 7, j = i & 127;
            g_WtN1[i] = W2a[j * 320 + k];
        }
    } else if (b == 130) {
        for (int i = t; i < 128 * 128; i += 128) {
            int k = i >> 7, j = i & 127;
            g_WtN2[i] = W2b[j * 128 + k];
        }
    } else { // 131: UW[g][j] = sum_k u[g,k]*W2a[j,256+k]
        for (int i = t; i < NGR * 128; i += 128) {
            int g = i >> 7, j = i & 127;
            float s = 0.f;
            for (int k = 0; k < 64; k++) s += u[g * 64 + k] * W2a[j * 320 + 256 + k];
            g_UW[i] = s;
        }
    }
}

// ---------------- generic 128x128 register-tiled GEMM ----------------
// MODE 0: H1  = x_h @ WtH1 + b1a                       (K=64)  -> g_H1
// MODE 1: edge GEMM: edge_attr @ WtE, epilogue adds H1[src], leaky, red -> g_S, deg  (K=64)
// MODE 2: node stage1: [x_g | g_S] @ WtN1 + b2a + deg*c + UW[batch], leaky (K=256) -> g_T2
// MODE 3: out = g_T2 @ WtN2 + b2b                      (K=128) -> Cout
template <int KTOT, int MODE>
__launch_bounds__(256)
__global__ void k_gemm(const float* __restrict__ A0, const float* __restrict__ bias,
                       float* __restrict__ Cout, int Mrows, const void* __restrict__ idx) {
    __shared__ float As[128 * 32];
    __shared__ float Bs[32 * 128];

    const int tid = threadIdx.x;
    const int tx = tid & 15, ty = tid >> 4;
    const int r0 = ty * 8, c0 = tx * 8;
    const int m0 = blockIdx.x * 128;

    const float* Bt = (MODE == 0) ? g_WtH1 : (MODE == 1) ? g_WtE : (MODE == 2) ? g_WtN1 : g_WtN2;

    float acc[8][8];
#pragma unroll
    for (int i = 0; i < 8; i++)
#pragma unroll
        for (int j = 0; j < 8; j++) acc[i][j] = 0.f;

    for (int ks = 0; ks < KTOT; ks += 32) {
        const float* Asrc;
        int koff, lda;
        if (MODE == 2) {
            lda = 128;
            if (ks < 128) { Asrc = A0;  koff = ks; }
            else          { Asrc = g_S; koff = ks - 128; }
        } else if (MODE == 3) {
            Asrc = g_T2; lda = 128; koff = ks;
        } else {
            Asrc = A0; lda = KTOT; koff = ks;
        }
        // load A tile [128 x 32] (1024 float4)
#pragma unroll
        for (int it = 0; it < 4; it++) {
            int q = tid + it * 256;
            int m = q >> 3, k4 = q & 7;
            float4 v = make_float4(0.f, 0.f, 0.f, 0.f);
            if (m0 + m < Mrows)
                v = ((const float4*)(Asrc + (long long)(m0 + m) * lda + koff))[k4];
            ((float4*)As)[q] = v;
        }
        // load B tile [32 x 128] (1024 float4), rows ks..ks+31 of Bt
#pragma unroll
        for (int it = 0; it < 4; it++) {
            int q = tid + it * 256;
            int k = q >> 5, j4 = q & 31;
            ((float4*)Bs)[q] = ((const float4*)(Bt + (long long)(ks + k) * 128))[j4];
        }
        __syncthreads();

#pragma unroll
        for (int kk4 = 0; kk4 < 8; kk4++) {
            float4 av[8];
#pragma unroll
            for (int i = 0; i < 8; i++) av[i] = ((const float4*)As)[(r0 + i) * 8 + kk4];
#pragma unroll
            for (int u = 0; u < 4; u++) {
                float4 b0 = ((const float4*)Bs)[(kk4 * 4 + u) * 32 + tx * 2];
                float4 b1 = ((const float4*)Bs)[(kk4 * 4 + u) * 32 + tx * 2 + 1];
                float bb[8] = {b0.x, b0.y, b0.z, b0.w, b1.x, b1.y, b1.z, b1.w};
#pragma unroll
                for (int i = 0; i < 8; i++) {
                    float a = (u == 0) ? av[i].x : (u == 1) ? av[i].y : (u == 2) ? av[i].z : av[i].w;
#pragma unroll
                    for (int j = 0; j < 8; j++) acc[i][j] = fmaf(a, bb[j], acc[i][j]);
                }
            }
        }
        __syncthreads();
    }

    // ---------------- epilogues ----------------
    if (MODE == 0 || MODE == 3) {
        float bloc[8];
#pragma unroll
        for (int j = 0; j < 8; j++) bloc[j] = bias[c0 + j];
        float* C = (MODE == 0) ? g_H1 : Cout;
#pragma unroll
        for (int i = 0; i < 8; i++) {
            int m = m0 + r0 + i;
            if (m < Mrows) {
                float4* dst = (float4*)(C + (long long)m * 128 + c0);
                dst[0] = make_float4(acc[i][0] + bloc[0], acc[i][1] + bloc[1],
                                     acc[i][2] + bloc[2], acc[i][3] + bloc[3]);
                dst[1] = make_float4(acc[i][4] + bloc[4], acc[i][5] + bloc[5],
                                     acc[i][6] + bloc[6], acc[i][7] + bloc[7]);
            }
        }
    }
    if (MODE == 1) {
        const int is64 = g_is64_e;
#pragma unroll
        for (int i = 0; i < 8; i++) {
            long long e = (long long)m0 + r0 + i;
            long long s, t;
            if (is64) {
                s = ((const long long*)idx)[e];
                t = ((const long long*)idx)[(long long)NE + e];
            } else {
                s = ((const int*)idx)[e];
                t = ((const int*)idx)[(long long)NE + e];
            }
            const float4* h = (const float4*)(g_H1 + s * 128 + c0);
            float4 h0 = h[0], h1 = h[1];
            float v[8];
            v[0] = acc[i][0] + h0.x; v[1] = acc[i][1] + h0.y;
            v[2] = acc[i][2] + h0.z; v[3] = acc[i][3] + h0.w;
            v[4] = acc[i][4] + h1.x; v[5] = acc[i][5] + h1.y;
            v[6] = acc[i][6] + h1.z; v[7] = acc[i][7] + h1.w;
#pragma unroll
            for (int j = 0; j < 8; j++) v[j] = (v[j] >= 0.f) ? v[j] : 0.1f * v[j];
            float* dst = g_S + t * 128 + c0;
            asm volatile("red.global.add.v4.f32 [%0], {%1,%2,%3,%4};"
                         :: "l"(dst), "f"(v[0]), "f"(v[1]), "f"(v[2]), "f"(v[3]) : "memory");
            asm volatile("red.global.add.v4.f32 [%0], {%1,%2,%3,%4};"
                         :: "l"(dst + 4), "f"(v[4]), "f"(v[5]), "f"(v[6]), "f"(v[7]) : "memory");
            if (tx == 0) atomicAdd(&g_deg[t], 1);
        }
    }
    if (MODE == 2) {
        const int is64 = g_is64_b;
        float bloc[8], cloc[8];
#pragma unroll
        for (int j = 0; j < 8; j++) { bloc[j] = bias[c0 + j]; cloc[j] = g_cvec[c0 + j]; }
#pragma unroll
        for (int i = 0; i < 8; i++) {
            int m = m0 + r0 + i;
            if (m < Mrows) {
                long long g = is64 ? ((const long long*)idx)[m] : (long long)((const int*)idx)[m];
                float dg = (float)g_deg[m];
                const float* uw = g_UW + g * 128 + c0;
                float v[8];
#pragma unroll
                for (int j = 0; j < 8; j++) {
                    float z = acc[i][j] + bloc[j] + dg * cloc[j] + uw[j];
                    v[j] = (z >= 0.f) ? z : 0.1f * z;
                }
                float4* dst = (float4*)(g_T2 + (long long)m * 128 + c0);
                dst[0] = make_float4(v[0], v[1], v[2], v[3]);
                dst[1] = make_float4(v[4], v[5], v[6], v[7]);
            }
        }
    }
}

// ---------------- launch ----------------
extern "C" void kernel_launch(void* const* d_in, const int* in_sizes, int n_in,
                              void* d_out, int out_size) {
    const float* x_h       = (const float*)d_in[0];
    const float* x_g       = (const float*)d_in[1];
    const float* edge_attr = (const float*)d_in[2];
    const float* u         = (const float*)d_in[3];
    const float* W1a       = (const float*)d_in[4];
    const float* b1a       = (const float*)d_in[5];
    const float* W1b       = (const float*)d_in[6];
    const float* b1b       = (const float*)d_in[7];
    const float* W2a       = (const float*)d_in[8];
    const float* b2a       = (const float*)d_in[9];
    const float* W2b       = (const float*)d_in[10];
    const float* b2b       = (const float*)d_in[11];
    const void*  eidx      = d_in[12];
    const void*  batch     = d_in[13];
    float* out = (float*)d_out;

    k_detect<<<1, 32>>>(eidx, batch);
    k_zero<<<512, 256>>>();
    k_prep<<<132, 128>>>(W1a, W1b, W2a, W2b, b1b, u);

    const int gb_nodes = (NGN + 127) / 128;   // 391
    const int gb_edges = NE / 128;            // 12500

    // H1 = x_h @ W1aL^T + b1a
    k_gemm<64, 0><<<gb_nodes, 256>>>(x_h, b1a, nullptr, NHN, nullptr);
    // edge GEMM + gather(H1[src]) + leaky + scatter-red to S / deg
    k_gemm<64, 1><<<gb_edges, 256>>>(edge_attr, nullptr, nullptr, NE, eidx);
    // node stage 1 (K=256: x_g then S), leaky -> T2
    k_gemm<256, 2><<<gb_nodes, 256>>>(x_g, b2a, nullptr, NGN, batch);
    // out = T2 @ W2b^T + b2b
    k_gemm<128, 3><<<gb_nodes, 256>>>(nullptr, b2b, out, NGN, nullptr);
}

// round 3
// speedup vs baseline: 1.0536x; 1.0536x over previous
#include <cuda_runtime.h>
#include <cstdint>

#define NHN 50000
#define NGN 50000
#define NE  1600000
#define NGR 16

// ---------------- scratch (device globals; no allocations) ----------------
__device__ __align__(16) float g_H1[(size_t)NHN * 128];   // x_h@W1aL^T + b1a (pre-activation partial)
__device__ __align__(16) float g_S [(size_t)NGN * 128];   // sum of leaky(z_e) per target node
__device__ __align__(16) float g_T2[(size_t)NGN * 128];   // leaky(node-MLP stage1)
__device__ __align__(16) float g_WtH1[64 * 128];          // W1a[:, :64]^T   -> [k][j]
__device__ __align__(16) float g_WtE [64 * 128];          // W1a[:, 64:]^T   -> [k][j]
__device__ __align__(16) float g_WtN1[256 * 128];         // rows 0:128 = W2a[:, :128]^T ; rows 128:256 = (W2aA@W1b)^T
__device__ __align__(16) float g_WtN2[128 * 128];         // W2b^T
__device__ __align__(16) float g_cvec[128];               // W2aA @ b1b
__device__ __align__(16) float g_UW[NGR * 128];           // u @ W2aU^T
__device__ int g_deg[NGN];
__device__ int g_is64_e;
__device__ int g_is64_b;

// ---------------- packed f32x2 helpers (Blackwell 2x fp32 pipe) ----------------
__device__ __forceinline__ unsigned long long pack2(float x) {
    unsigned long long r;
    asm("mov.b64 %0, {%1, %1};" : "=l"(r) : "f"(x));
    return r;
}
__device__ __forceinline__ void ffma2(unsigned long long& c, unsigned long long a,
                                      unsigned long long b) {
    asm("fma.rn.f32x2 %0, %1, %2, %0;" : "+l"(c) : "l"(a), "l"(b));
}
__device__ __forceinline__ float2 unpack2(unsigned long long v) {
    float2 f;
    asm("mov.b64 {%0, %1}, %2;" : "=f"(f.x), "=f"(f.y) : "l"(v));
    return f;
}

// ---------------- dtype detection (int32 vs int64 indices) ----------------
__global__ void k_detect(const void* eidx, const void* batch) {
    if (blockIdx.x == 0 && threadIdx.x == 0) {
        const unsigned* p = (const unsigned*)eidx;
        int is64 = 1;
        for (int i = 0; i < 32; i++) {
            unsigned lo = p[2 * i], hi = p[2 * i + 1];
            if (hi != 0u || lo >= (unsigned)NHN) { is64 = 0; break; }
        }
        g_is64_e = is64;
        const unsigned* q = (const unsigned*)batch;
        int b64 = 1;
        for (int i = 0; i < 32; i++) {
            unsigned lo = q[2 * i], hi = q[2 * i + 1];
            if (hi != 0u || lo >= (unsigned)NGR) { b64 = 0; break; }
        }
        g_is64_b = b64;
    }
}

// ---------------- zero scratch ----------------
__global__ void k_zero() {
    long long n4 = (long long)NGN * 128 / 4;
    long long stride = (long long)gridDim.x * blockDim.x;
    for (long long i = (long long)blockIdx.x * blockDim.x + threadIdx.x; i < n4; i += stride)
        ((float4*)g_S)[i] = make_float4(0.f, 0.f, 0.f, 0.f);
    for (long long i = (long long)blockIdx.x * blockDim.x + threadIdx.x; i < NGN; i += stride)
        g_deg[i] = 0;
}

// ---------------- weight precompute / transposes ----------------
__global__ void k_prep(const float* __restrict__ W1a, const float* __restrict__ W1b,
                       const float* __restrict__ W2a, const float* __restrict__ W2b,
                       const float* __restrict__ b1b, const float* __restrict__ u) {
    int b = blockIdx.x, t = threadIdx.x;
    if (b < 128) {
        // M[j=b][k=t] = sum_p W2a[j,128+p] * W1b[p,k]; stored transposed at g_WtN1[(128+k)*128 + j]
        __shared__ float wrow[128];
        wrow[t] = W2a[b * 320 + 128 + t];
        __syncthreads();
        float s = 0.f;
        for (int p = 0; p < 128; p++) s += wrow[p] * W1b[p * 128 + t];
        g_WtN1[(128 + t) * 128 + b] = s;
        if (t == 0) {
            float c = 0.f;
            for (int p = 0; p < 128; p++) c += wrow[p] * b1b[p];
            g_cvec[b] = c;
        }
    } else if (b == 128) {
        for (int i = t; i < 64 * 128; i += 128) {
            int k = i >> 7, j = i & 127;
            g_WtH1[i] = W1a[j * 128 + k];
            g_WtE[i]  = W1a[j * 128 + 64 + k];
        }
    } else if (b == 129) {
        for (int i = t; i < 128 * 128; i += 128) {
            int k = i >> 7, j = i & 127;
            g_WtN1[i] = W2a[j * 320 + k];
        }
    } else if (b == 130) {
        for (int i = t; i < 128 * 128; i += 128) {
            int k = i >> 7, j = i & 127;
            g_WtN2[i] = W2b[j * 128 + k];
        }
    } else { // 131: UW[g][j] = sum_k u[g,k]*W2a[j,256+k]
        for (int i = t; i < NGR * 128; i += 128) {
            int g = i >> 7, j = i & 127;
            float s = 0.f;
            for (int k = 0; k < 64; k++) s += u[g * 64 + k] * W2a[j * 320 + 256 + k];
            g_UW[i] = s;
        }
    }
}

// ---------------- generic 128x128 register-tiled GEMM (f32x2 packed math) ----------------
// MODE 0: H1  = x_h @ WtH1 + b1a                       (K=64)  -> g_H1
// MODE 1: edge GEMM: edge_attr @ WtE, epilogue adds H1[src], leaky, red -> g_S, deg  (K=64)
// MODE 2: node stage1: [x_g | g_S] @ WtN1 + b2a + deg*c + UW[batch], leaky (K=256) -> g_T2
// MODE 3: out = g_T2 @ WtN2 + b2b                      (K=128) -> Cout
template <int KTOT, int MODE>
__launch_bounds__(256)
__global__ void k_gemm(const float* __restrict__ A0, const float* __restrict__ bias,
                       float* __restrict__ Cout, int Mrows, const void* __restrict__ idx) {
    __shared__ float As[128 * 32];
    __shared__ float Bs[32 * 128];

    const int tid = threadIdx.x;
    const int tx = tid & 15, ty = tid >> 4;
    const int r0 = ty * 8, c0 = tx * 8;
    const int m0 = blockIdx.x * 128;

    const float* Bt = (MODE == 0) ? g_WtH1 : (MODE == 1) ? g_WtE : (MODE == 2) ? g_WtN1 : g_WtN2;

    // packed accumulators: acc2[i][j2] holds columns (c0+2*j2, c0+2*j2+1), x=lower
    unsigned long long acc2[8][4];
#pragma unroll
    for (int i = 0; i < 8; i++)
#pragma unroll
        for (int j = 0; j < 4; j++) acc2[i][j] = 0ull;

    for (int ks = 0; ks < KTOT; ks += 32) {
        const float* Asrc;
        int koff, lda;
        if (MODE == 2) {
            lda = 128;
            if (ks < 128) { Asrc = A0;  koff = ks; }
            else          { Asrc = g_S; koff = ks - 128; }
        } else if (MODE == 3) {
            Asrc = g_T2; lda = 128; koff = ks;
        } else {
            Asrc = A0; lda = KTOT; koff = ks;
        }
        // load A tile [128 x 32] (1024 float4)
#pragma unroll
        for (int it = 0; it < 4; it++) {
            int q = tid + it * 256;
            int m = q >> 3, k4 = q & 7;
            float4 v = make_float4(0.f, 0.f, 0.f, 0.f);
            if (m0 + m < Mrows)
                v = ((const float4*)(Asrc + (long long)(m0 + m) * lda + koff))[k4];
            ((float4*)As)[q] = v;
        }
        // load B tile [32 x 128] (1024 float4), rows ks..ks+31 of Bt
#pragma unroll
        for (int it = 0; it < 4; it++) {
            int q = tid + it * 256;
            ((float4*)Bs)[q] = ((const float4*)Bt)[(long long)(ks * 32) + q];
        }
        __syncthreads();

#pragma unroll
        for (int kk4 = 0; kk4 < 8; kk4++) {
            float4 av[8];
#pragma unroll
            for (int i = 0; i < 8; i++) av[i] = ((const float4*)As)[(r0 + i) * 8 + kk4];
#pragma unroll
            for (int u = 0; u < 4; u++) {
                // B packs: adjacent columns are natural (b[j], b[j+1]) f32x2 pairs
                const ulonglong2* bp =
                    (const ulonglong2*)(Bs + (kk4 * 4 + u) * 128 + c0);
                ulonglong2 b0 = bp[0];
                ulonglong2 b1 = bp[1];
#pragma unroll
                for (int i = 0; i < 8; i++) {
                    float a = (u == 0) ? av[i].x : (u == 1) ? av[i].y
                             : (u == 2) ? av[i].z : av[i].w;
                    unsigned long long a2 = pack2(a);
                    ffma2(acc2[i][0], a2, b0.x);
                    ffma2(acc2[i][1], a2, b0.y);
                    ffma2(acc2[i][2], a2, b1.x);
                    ffma2(acc2[i][3], a2, b1.y);
                }
            }
        }
        __syncthreads();
    }

    // unpack accumulators
    float acc[8][8];
#pragma unroll
    for (int i = 0; i < 8; i++)
#pragma unroll
        for (int j = 0; j < 4; j++) {
            float2 f = unpack2(acc2[i][j]);
            acc[i][2 * j]     = f.x;
            acc[i][2 * j + 1] = f.y;
        }

    // ---------------- epilogues ----------------
    if (MODE == 0 || MODE == 3) {
        float bloc[8];
#pragma unroll
        for (int j = 0; j < 8; j++) bloc[j] = bias[c0 + j];
        float* C = (MODE == 0) ? g_H1 : Cout;
#pragma unroll
        for (int i = 0; i < 8; i++) {
            int m = m0 + r0 + i;
            if (m < Mrows) {
                float4* dst = (float4*)(C + (long long)m * 128 + c0);
                dst[0] = make_float4(acc[i][0] + bloc[0], acc[i][1] + bloc[1],
                                     acc[i][2] + bloc[2], acc[i][3] + bloc[3]);
                dst[1] = make_float4(acc[i][4] + bloc[4], acc[i][5] + bloc[5],
                                     acc[i][6] + bloc[6], acc[i][7] + bloc[7]);
            }
        }
    }
    if (MODE == 1) {
        const int is64 = g_is64_e;
#pragma unroll
        for (int i = 0; i < 8; i++) {
            long long e = (long long)m0 + r0 + i;
            long long s, t;
            if (is64) {
                s = ((const long long*)idx)[e];
                t = ((const long long*)idx)[(long long)NE + e];
            } else {
                s = ((const int*)idx)[e];
                t = ((const int*)idx)[(long long)NE + e];
            }
            const float4* h = (const float4*)(g_H1 + s * 128 + c0);
            float4 h0 = h[0], h1 = h[1];
            float v[8];
            v[0] = acc[i][0] + h0.x; v[1] = acc[i][1] + h0.y;
            v[2] = acc[i][2] + h0.z; v[3] = acc[i][3] + h0.w;
            v[4] = acc[i][4] + h1.x; v[5] = acc[i][5] + h1.y;
            v[6] = acc[i][6] + h1.z; v[7] = acc[i][7] + h1.w;
#pragma unroll
            for (int j = 0; j < 8; j++) v[j] = (v[j] >= 0.f) ? v[j] : 0.1f * v[j];
            float* dst = g_S + t * 128 + c0;
            asm volatile("red.global.add.v4.f32 [%0], {%1,%2,%3,%4};"
                         :: "l"(dst), "f"(v[0]), "f"(v[1]), "f"(v[2]), "f"(v[3]) : "memory");
            asm volatile("red.global.add.v4.f32 [%0], {%1,%2,%3,%4};"
                         :: "l"(dst + 4), "f"(v[4]), "f"(v[5]), "f"(v[6]), "f"(v[7]) : "memory");
            if (tx == 0) atomicAdd(&g_deg[t], 1);
        }
    }
    if (MODE == 2) {
        const int is64 = g_is64_b;
        float bloc[8], cloc[8];
#pragma unroll
        for (int j = 0; j < 8; j++) { bloc[j] = bias[c0 + j]; cloc[j] = g_cvec[c0 + j]; }
#pragma unroll
        for (int i = 0; i < 8; i++) {
            int m = m0 + r0 + i;
            if (m < Mrows) {
                long long g = is64 ? ((const long long*)idx)[m] : (long long)((const int*)idx)[m];
                float dg = (float)g_deg[m];
                const float* uw = g_UW + g * 128 + c0;
                float v[8];
#pragma unroll
                for (int j = 0; j < 8; j++) {
                    float z = acc[i][j] + bloc[j] + dg * cloc[j] + uw[j];
                    v[j] = (z >= 0.f) ? z : 0.1f * z;
                }
                float4* dst = (float4*)(g_T2 + (long long)m * 128 + c0);
                dst[0] = make_float4(v[0], v[1], v[2], v[3]);
                dst[1] = make_float4(v[4], v[5], v[6], v[7]);
            }
        }
    }
}

// ---------------- launch ----------------
extern "C" void kernel_launch(void* const* d_in, const int* in_sizes, int n_in,
                              void* d_out, int out_size) {
    const float* x_h       = (const float*)d_in[0];
    const float* x_g       = (const float*)d_in[1];
    const float* edge_attr = (const float*)d_in[2];
    const float* u         = (const float*)d_in[3];
    const float* W1a       = (const float*)d_in[4];
    const float* b1a       = (const float*)d_in[5];
    const float* W1b       = (const float*)d_in[6];
    const float* b1b       = (const float*)d_in[7];
    const float* W2a       = (const float*)d_in[8];
    const float* b2a       = (const float*)d_in[9];
    const float* W2b       = (const float*)d_in[10];
    const float* b2b       = (const float*)d_in[11];
    const void*  eidx      = d_in[12];
    const void*  batch     = d_in[13];
    float* out = (float*)d_out;

    k_detect<<<1, 32>>>(eidx, batch);
    k_zero<<<512, 256>>>();
    k_prep<<<132, 128>>>(W1a, W1b, W2a, W2b, b1b, u);

    const int gb_nodes = (NGN + 127) / 128;   // 391
    const int gb_edges = NE / 128;            // 12500

    // H1 = x_h @ W1aL^T + b1a
    k_gemm<64, 0><<<gb_nodes, 256>>>(x_h, b1a, nullptr, NHN, nullptr);
    // edge GEMM + gather(H1[src]) + leaky + scatter-red to S / deg
    k_gemm<64, 1><<<gb_edges, 256>>>(edge_attr, nullptr, nullptr, NE, eidx);
    // node stage 1 (K=256: x_g then S), leaky -> T2
    k_gemm<256, 2><<<gb_nodes, 256>>>(x_g, b2a, nullptr, NGN, batch);
    // out = T2 @ W2b^T + b2b
    k_gemm<128, 3><<<gb_nodes, 256>>>(nullptr, b2b, out, NGN, nullptr);
}